// round 6
// baseline (speedup 1.0000x reference)
#include <cuda_runtime.h>
#include <cuda_fp16.h>
#include <cstdint>

// Problem-fixed dims: B=4, S=2048 -> M=8192, D=2048, R=512.
#define MM 8192
#define DD 2048
#define RR 512

// Scratch (device globals; no allocation allowed in kernel_launch).
__device__ __half g_x16[MM * (size_t)DD];   // x cast to fp16, [M][D]
__device__ __half g_h[MM * (size_t)RR];     // stage-1 output fp16, [M][R]
__device__ __half g_win[(size_t)RR * DD];   // B^T for stage 1: [N=R][K=D]
__device__ __half g_wout[(size_t)DD * RR];  // B^T for stage 2: [N=D][K=R]

// ---------------------------------------------------------------------------
// helpers
// ---------------------------------------------------------------------------
__device__ __forceinline__ uint32_t smem_u32(const void* p) {
    return (uint32_t)__cvta_generic_to_shared(p);
}
__device__ __forceinline__ void cp_async16(uint32_t saddr, const void* gaddr) {
    asm volatile("cp.async.cg.shared.global [%0], [%1], 16;\n"
                 :: "r"(saddr), "l"(gaddr));
}
__device__ __forceinline__ void cp_commit() {
    asm volatile("cp.async.commit_group;\n");
}
template<int N>
__device__ __forceinline__ void cp_wait() {
    asm volatile("cp.async.wait_group %0;\n" :: "n"(N));
}
__device__ __forceinline__ void ldsm4(uint32_t* r, uint32_t addr) {
    asm volatile("ldmatrix.sync.aligned.m8n8.x4.shared.b16 {%0,%1,%2,%3}, [%4];\n"
                 : "=r"(r[0]), "=r"(r[1]), "=r"(r[2]), "=r"(r[3])
                 : "r"(addr));
}
__device__ __forceinline__ void mma16816(float* c, const uint32_t* a, const uint32_t* b) {
    asm volatile(
        "mma.sync.aligned.m16n8k16.row.col.f32.f16.f16.f32 "
        "{%0,%1,%2,%3}, {%4,%5,%6,%7}, {%8,%9}, {%0,%1,%2,%3};\n"
        : "+f"(c[0]), "+f"(c[1]), "+f"(c[2]), "+f"(c[3])
        : "r"(a[0]), "r"(a[1]), "r"(a[2]), "r"(a[3]), "r"(b[0]), "r"(b[1]));
}

// ---------------------------------------------------------------------------
// preprocessing kernels
// ---------------------------------------------------------------------------
__global__ void convert_x_kernel(const float* __restrict__ x) {
    size_t i = ((size_t)blockIdx.x * blockDim.x + threadIdx.x) * 8;
    float4 a = *(const float4*)(x + i);
    float4 b = *(const float4*)(x + i + 4);
    __half2 h0 = __floats2half2_rn(a.x, a.y);
    __half2 h1 = __floats2half2_rn(a.z, a.w);
    __half2 h2 = __floats2half2_rn(b.x, b.y);
    __half2 h3 = __floats2half2_rn(b.z, b.w);
    uint4 v;
    v.x = *(uint32_t*)&h0; v.y = *(uint32_t*)&h1;
    v.z = *(uint32_t*)&h2; v.w = *(uint32_t*)&h3;
    *(uint4*)(g_x16 + i) = v;
}

__device__ __forceinline__ float second_smallest4(float a0, float a1, float a2, float a3) {
    float lo01 = fminf(a0, a1), hi01 = fmaxf(a0, a1);
    float lo23 = fminf(a2, a3), hi23 = fmaxf(a2, a3);
    return fminf(fmaxf(lo01, lo23), fminf(hi01, hi23));
}
__device__ __forceinline__ float shrink1(float w, float t, float s) {
    float a = fabsf(w) - t;
    a = a > 0.f ? a : 0.f;
    return copysignf(a, w) * s;
}

__global__ void prep_win_kernel(const float* __restrict__ w, const float* __restrict__ scale_p) {
    int idx = blockIdx.x * blockDim.x + threadIdx.x;
    int d  = idx >> 7;
    int rg = idx & 127;
    float4 wv = *(const float4*)(w + (size_t)d * RR + rg * 4);
    float s = *scale_p;
    float t = second_smallest4(fabsf(wv.x), fabsf(wv.y), fabsf(wv.z), fabsf(wv.w));
    int r0 = rg * 4;
    g_win[(size_t)(r0 + 0) * DD + d] = __float2half_rn(shrink1(wv.x, t, s));
    g_win[(size_t)(r0 + 1) * DD + d] = __float2half_rn(shrink1(wv.y, t, s));
    g_win[(size_t)(r0 + 2) * DD + d] = __float2half_rn(shrink1(wv.z, t, s));
    g_win[(size_t)(r0 + 3) * DD + d] = __float2half_rn(shrink1(wv.w, t, s));
}

__global__ void prep_wout_kernel(const float* __restrict__ w, const float* __restrict__ scale_p) {
    int idx = blockIdx.x * blockDim.x + threadIdx.x;
    int dg = idx >> 9;
    int r  = idx & 511;
    int d0 = dg * 4;
    float w0 = w[(size_t)(d0 + 0) * RR + r];
    float w1 = w[(size_t)(d0 + 1) * RR + r];
    float w2 = w[(size_t)(d0 + 2) * RR + r];
    float w3 = w[(size_t)(d0 + 3) * RR + r];
    float s = *scale_p;
    float t = second_smallest4(fabsf(w0), fabsf(w1), fabsf(w2), fabsf(w3));
    g_wout[(size_t)(d0 + 0) * RR + r] = __float2half_rn(shrink1(w0, t, s));
    g_wout[(size_t)(d0 + 1) * RR + r] = __float2half_rn(shrink1(w1, t, s));
    g_wout[(size_t)(d0 + 2) * RR + r] = __float2half_rn(shrink1(w2, t, s));
    g_wout[(size_t)(d0 + 3) * RR + r] = __float2half_rn(shrink1(w3, t, s));
}

// ---------------------------------------------------------------------------
// HMMA GEMM: C[M][N] = A[M][K] * Bt[N][K], fp16 in, fp32 acc.
// BM=128, BN=128, BK=64. 128 threads, 4 warps in 2x2, warp tile 64x64.
// DEPTH=3: cp.async ring with prefetch distance 2 (regs up to 255, 2 CTAs/SM).
// DEPTH=2: prefetch distance 1, 64KB smem, MAXCTAS=3 -> 3 CTAs/SM.
// ---------------------------------------------------------------------------
template<int DEPTH, int MAXCTAS, typename OutT, bool HAS_BIAS>
__global__ __launch_bounds__(128, MAXCTAS) void gemm_tc(
    const __half* __restrict__ A, const __half* __restrict__ Bt,
    OutT* __restrict__ C, const float* __restrict__ bias, int K, int N)
{
    constexpr int ABYTES = 128 * 128;      // 128 rows x 64 halves
    constexpr int STAGE  = 2 * ABYTES;     // A + B

    extern __shared__ __align__(1024) uint8_t dsmem[];
    const uint32_t sbase = (smem_u32(dsmem) + 1023u) & ~1023u;

    const int tid = threadIdx.x;
    const int wid = tid >> 5, ln = tid & 31;
    const int bm = blockIdx.y * 128, bn = blockIdx.x * 128;
    const int warpM = (wid >> 1) * 64;
    const int warpN = (wid & 1) * 64;

    float acc[4][8][4];
#pragma unroll
    for (int i = 0; i < 4; i++)
#pragma unroll
        for (int j = 0; j < 8; j++)
#pragma unroll
            for (int k = 0; k < 4; k++) acc[i][j][k] = 0.f;

    // ldmatrix fragment row addressing (chunk computed per ks)
    const int mat = ln >> 3;       // 0..3
    const int mr  = ln & 7;
    const int aHi = mat >> 1;
    const int bHi = mat & 1;
    uint32_t aRowOff[4]; int aRx[4];
#pragma unroll
    for (int mt = 0; mt < 4; mt++) {
        int row = warpM + mt * 16 + ((mat & 1) << 3) + mr;
        aRowOff[mt] = (uint32_t)(row * 128);
        aRx[mt] = row & 7;
    }
    uint32_t bRowOff[4]; int bRx[4];
#pragma unroll
    for (int np = 0; np < 4; np++) {
        int row = warpN + np * 16 + ((mat >> 1) << 3) + mr;
        bRowOff[np] = (uint32_t)(row * 128);
        bRx[np] = row & 7;
    }

    const int KT = K >> 6;

    auto load_stage = [&](int kt, int s) {
        const uint32_t aS = sbase + (uint32_t)s * STAGE;
        const uint32_t bS = aS + ABYTES;
        const __half* Ag = A  + (size_t)bm * K + (size_t)kt * 64;
        const __half* Bg = Bt + (size_t)bn * K + (size_t)kt * 64;
#pragma unroll
        for (int i = 0; i < 8; i++) {
            int l = tid + i * 128;
            int row = l >> 3, kc = l & 7;
            uint32_t soff = (uint32_t)(row * 128 + ((kc ^ (row & 7)) * 16));
            cp_async16(aS + soff, Ag + (size_t)row * K + kc * 8);
            cp_async16(bS + soff, Bg + (size_t)row * K + kc * 8);
        }
        cp_commit();
    };

    auto compute_tile = [&](int s) {
        const uint32_t aB = sbase + (uint32_t)s * STAGE;
        const uint32_t bB = aB + ABYTES;
#pragma unroll
        for (int ks = 0; ks < 4; ks++) {
            uint32_t af[4][4];
#pragma unroll
            for (int mt = 0; mt < 4; mt++)
                ldsm4(af[mt], aB + aRowOff[mt] + (uint32_t)((((2 * ks + aHi) ^ aRx[mt])) * 16));
            uint32_t bf[8][2];
#pragma unroll
            for (int np = 0; np < 4; np++) {
                uint32_t t[4];
                ldsm4(t, bB + bRowOff[np] + (uint32_t)((((2 * ks + bHi) ^ bRx[np])) * 16));
                bf[2 * np][0] = t[0]; bf[2 * np][1] = t[1];
                bf[2 * np + 1][0] = t[2]; bf[2 * np + 1][1] = t[3];
            }
#pragma unroll
            for (int mt = 0; mt < 4; mt++)
#pragma unroll
                for (int nt = 0; nt < 8; nt++)
                    mma16816(acc[mt][nt], af[mt], bf[nt]);
        }
    };

    if constexpr (DEPTH == 3) {
        load_stage(0, 0);
        load_stage(1, 1);
        for (int kt = 0; kt < KT; kt++) {
            cp_wait<1>();
            __syncthreads();
            if (kt + 2 < KT) load_stage(kt + 2, (kt + 2) % 3);
            else cp_commit();
            compute_tile(kt % 3);
        }
    } else {   // DEPTH == 2, prefetch distance 1
        load_stage(0, 0);
        for (int kt = 0; kt < KT; kt++) {
            cp_wait<0>();
            __syncthreads();
            if (kt + 1 < KT) load_stage(kt + 1, (kt + 1) & 1);
            compute_tile(kt & 1);
        }
    }

    // epilogue
#pragma unroll
    for (int mt = 0; mt < 4; mt++) {
#pragma unroll
        for (int nt = 0; nt < 8; nt++) {
            int m0 = bm + warpM + mt * 16 + (ln >> 2);
            int n0 = bn + warpN + nt * 8 + (ln & 3) * 2;
            float* a = acc[mt][nt];
            if constexpr (HAS_BIAS) {
                float b0 = bias[n0], b1 = bias[n0 + 1];
                float2 v0 = make_float2(a[0] + b0, a[1] + b1);
                float2 v1 = make_float2(a[2] + b0, a[3] + b1);
                *(float2*)((float*)C + (size_t)m0 * N + n0)       = v0;
                *(float2*)((float*)C + (size_t)(m0 + 8) * N + n0) = v1;
            } else {
                __half2 v0 = __floats2half2_rn(a[0], a[1]);
                __half2 v1 = __floats2half2_rn(a[2], a[3]);
                *(__half2*)((__half*)C + (size_t)m0 * N + n0)       = v0;
                *(__half2*)((__half*)C + (size_t)(m0 + 8) * N + n0) = v1;
            }
        }
    }
}

// ---------------------------------------------------------------------------
extern "C" void kernel_launch(void* const* d_in, const int* in_sizes, int n_in,
                              void* d_out, int out_size)
{
    const float* x    = (const float*)d_in[0];
    const float* w_in = (const float*)d_in[1];
    const float* w_out= (const float*)d_in[2];
    const float* bias = (const float*)d_in[3];
    const float* s_in = (const float*)d_in[4];
    const float* s_out= (const float*)d_in[5];
    float* out = (float*)d_out;

    __half *x16, *h, *win, *wout;
    cudaGetSymbolAddress((void**)&x16,  g_x16);
    cudaGetSymbolAddress((void**)&h,    g_h);
    cudaGetSymbolAddress((void**)&win,  g_win);
    cudaGetSymbolAddress((void**)&wout, g_wout);

    constexpr int SMEM3 = 3 * (2 * 128 * 128) + 1024;   // stage-1: 3-deep ring
    constexpr int SMEM2 = 2 * (2 * 128 * 128) + 1024;   // stage-2: 2-deep ring

    cudaFuncSetAttribute(gemm_tc<3, 2, __half, false>,
                         cudaFuncAttributeMaxDynamicSharedMemorySize, SMEM3);
    cudaFuncSetAttribute(gemm_tc<2, 3, float, true>,
                         cudaFuncAttributeMaxDynamicSharedMemorySize, SMEM2);

    // 1) x fp32 -> fp16
    convert_x_kernel<<<(MM * (size_t)DD) / (256 * 8), 256>>>(x);
    // 2) soft-threshold weights into B^T fp16 layouts
    prep_win_kernel<<<(DD * (RR / 4)) / 256, 256>>>(w_in, s_in);
    prep_wout_kernel<<<((DD / 4) * RR) / 256, 256>>>(w_out, s_out);

    // 3) stage 1: h[M][R] = x16 @ win^T   grid (4, 64) = 256 CTAs, 2 CTAs/SM
    {
        dim3 grid(RR / 128, MM / 128);
        gemm_tc<3, 2, __half, false><<<grid, 128, SMEM3>>>(x16, win, h, nullptr, DD, RR);
    }
    // 4) stage 2: out[M][D] = h @ wout^T + bias  grid (16, 64) = 1024 CTAs, 3 CTAs/SM
    {
        dim3 grid(DD / 128, MM / 128);
        gemm_tc<2, 3, float, true><<<grid, 128, SMEM2>>>(h, wout, out, bias, RR, DD);
    }
}

// round 7
// speedup vs baseline: 1.1195x; 1.1195x over previous
#include <cuda_runtime.h>
#include <cuda_fp16.h>
#include <cstdint>

// Problem-fixed dims: B=4, S=2048 -> M=8192, D=2048, R=512.
#define MM 8192
#define DD 2048
#define RR 512

// Scratch (device globals; no allocation allowed in kernel_launch).
__device__ __half g_h[MM * (size_t)RR];     // stage-1 output fp16, [M][R]
__device__ __half g_win[(size_t)RR * DD];   // B^T for stage 1: [N=R][K=D]
__device__ __half g_wout[(size_t)DD * RR];  // B^T for stage 2: [N=D][K=R]

// ---------------------------------------------------------------------------
// helpers
// ---------------------------------------------------------------------------
__device__ __forceinline__ uint32_t smem_u32(const void* p) {
    return (uint32_t)__cvta_generic_to_shared(p);
}
__device__ __forceinline__ void cp_async16(uint32_t saddr, const void* gaddr) {
    asm volatile("cp.async.cg.shared.global [%0], [%1], 16;\n"
                 :: "r"(saddr), "l"(gaddr));
}
__device__ __forceinline__ void cp_commit() {
    asm volatile("cp.async.commit_group;\n");
}
template<int N>
__device__ __forceinline__ void cp_wait() {
    asm volatile("cp.async.wait_group %0;\n" :: "n"(N));
}
__device__ __forceinline__ void ldsm4(uint32_t* r, uint32_t addr) {
    asm volatile("ldmatrix.sync.aligned.m8n8.x4.shared.b16 {%0,%1,%2,%3}, [%4];\n"
                 : "=r"(r[0]), "=r"(r[1]), "=r"(r[2]), "=r"(r[3])
                 : "r"(addr));
}
__device__ __forceinline__ float2 lds_f2(uint32_t a) {
    float2 v;
    asm volatile("ld.shared.v2.f32 {%0,%1}, [%2];\n"
                 : "=f"(v.x), "=f"(v.y) : "r"(a));
    return v;
}
__device__ __forceinline__ void mma16816(float* c, const uint32_t* a, const uint32_t* b) {
    asm volatile(
        "mma.sync.aligned.m16n8k16.row.col.f32.f16.f16.f32 "
        "{%0,%1,%2,%3}, {%4,%5,%6,%7}, {%8,%9}, {%0,%1,%2,%3};\n"
        : "+f"(c[0]), "+f"(c[1]), "+f"(c[2]), "+f"(c[3])
        : "r"(a[0]), "r"(a[1]), "r"(a[2]), "r"(a[3]), "r"(b[0]), "r"(b[1]));
}

// ---------------------------------------------------------------------------
// preprocessing kernels (weights only; x conversion is fused into stage 1)
// ---------------------------------------------------------------------------
__device__ __forceinline__ float second_smallest4(float a0, float a1, float a2, float a3) {
    float lo01 = fminf(a0, a1), hi01 = fmaxf(a0, a1);
    float lo23 = fminf(a2, a3), hi23 = fmaxf(a2, a3);
    return fminf(fmaxf(lo01, lo23), fminf(hi01, hi23));
}
__device__ __forceinline__ float shrink1(float w, float t, float s) {
    float a = fabsf(w) - t;
    a = a > 0.f ? a : 0.f;
    return copysignf(a, w) * s;
}

__global__ void prep_win_kernel(const float* __restrict__ w, const float* __restrict__ scale_p) {
    int idx = blockIdx.x * blockDim.x + threadIdx.x;
    int d  = idx >> 7;
    int rg = idx & 127;
    float4 wv = *(const float4*)(w + (size_t)d * RR + rg * 4);
    float s = *scale_p;
    float t = second_smallest4(fabsf(wv.x), fabsf(wv.y), fabsf(wv.z), fabsf(wv.w));
    int r0 = rg * 4;
    g_win[(size_t)(r0 + 0) * DD + d] = __float2half_rn(shrink1(wv.x, t, s));
    g_win[(size_t)(r0 + 1) * DD + d] = __float2half_rn(shrink1(wv.y, t, s));
    g_win[(size_t)(r0 + 2) * DD + d] = __float2half_rn(shrink1(wv.z, t, s));
    g_win[(size_t)(r0 + 3) * DD + d] = __float2half_rn(shrink1(wv.w, t, s));
}

__global__ void prep_wout_kernel(const float* __restrict__ w, const float* __restrict__ scale_p) {
    int idx = blockIdx.x * blockDim.x + threadIdx.x;
    int dg = idx >> 9;
    int r  = idx & 511;
    int d0 = dg * 4;
    float w0 = w[(size_t)(d0 + 0) * RR + r];
    float w1 = w[(size_t)(d0 + 1) * RR + r];
    float w2 = w[(size_t)(d0 + 2) * RR + r];
    float w3 = w[(size_t)(d0 + 3) * RR + r];
    float s = *scale_p;
    float t = second_smallest4(fabsf(w0), fabsf(w1), fabsf(w2), fabsf(w3));
    g_wout[(size_t)(d0 + 0) * RR + r] = __float2half_rn(shrink1(w0, t, s));
    g_wout[(size_t)(d0 + 1) * RR + r] = __float2half_rn(shrink1(w1, t, s));
    g_wout[(size_t)(d0 + 2) * RR + r] = __float2half_rn(shrink1(w2, t, s));
    g_wout[(size_t)(d0 + 3) * RR + r] = __float2half_rn(shrink1(w3, t, s));
}

// ---------------------------------------------------------------------------
// Stage 1: h[M][R] = fp16(x[M][D]) @ win^T, x read as fp32 directly.
// BM=128, BN=128, BK=64, DEPTH=2 ring (A fp32 32KB + B fp16 16KB per stage).
// 128 threads, 4 warps 2x2, warp tile 64x64.
// A fragments built via ld.shared.v2.f32 + cvt (conflict-free swizzle),
// B fragments via ldmatrix as before.
// ---------------------------------------------------------------------------
__global__ __launch_bounds__(128, 2) void gemm_s1(
    const float* __restrict__ A, const __half* __restrict__ Bt,
    __half* __restrict__ C, int K, int N)
{
    constexpr int ABYTES = 128 * 256;      // 128 rows x 64 fp32
    constexpr int BBYTES = 128 * 128;      // 128 rows x 64 halves
    constexpr int STAGE  = ABYTES + BBYTES;

    extern __shared__ __align__(1024) uint8_t dsmem[];
    const uint32_t sbase = (smem_u32(dsmem) + 1023u) & ~1023u;

    const int tid = threadIdx.x;
    const int wid = tid >> 5, ln = tid & 31;
    const int bm = blockIdx.y * 128, bn = blockIdx.x * 128;
    const int warpM = (wid >> 1) * 64;
    const int warpN = (wid & 1) * 64;

    float acc[4][8][4];
#pragma unroll
    for (int i = 0; i < 4; i++)
#pragma unroll
        for (int j = 0; j < 8; j++)
#pragma unroll
            for (int k = 0; k < 4; k++) acc[i][j][k] = 0.f;

    // A fragment addressing: halfrow hr = 2*row + (ks>>1)
    const int aSub = (ln & 1) * 8;             // 8B select inside 16B chunk
    const int kBit = (ln & 3) >> 1;            // chunk low bit
    uint32_t aHr[4];                           // 2*row for each mt
#pragma unroll
    for (int mt = 0; mt < 4; mt++)
        aHr[mt] = (uint32_t)(2 * (warpM + mt * 16 + (ln >> 2)));

    // B fragment addressing (ldmatrix, as before)
    const int mat = ln >> 3;
    const int mr  = ln & 7;
    const int bHi = mat & 1;
    uint32_t bRowOff[4]; int bRx[4];
#pragma unroll
    for (int np = 0; np < 4; np++) {
        int row = warpN + np * 16 + ((mat >> 1) << 3) + mr;
        bRowOff[np] = (uint32_t)(row * 128);
        bRx[np] = row & 7;
    }

    const int KT = K >> 6;   // 32

    auto load_stage = [&](int kt, int s) {
        const uint32_t aS = sbase + (uint32_t)s * STAGE;
        const uint32_t bS = aS + ABYTES;
        const float*  Ag = A  + (size_t)bm * K + (size_t)kt * 64;
        const __half* Bg = Bt + (size_t)bn * K + (size_t)kt * 64;
#pragma unroll
        for (int i = 0; i < 16; i++) {         // A: 2048 16B chunks fp32
            int l = tid + i * 128;
            int hr = l >> 3, c = l & 7;        // hr: row*2+half, c: 4-float chunk
            uint32_t soff = (uint32_t)(hr * 128 + ((c ^ (hr & 7)) << 4));
            cp_async16(aS + soff, Ag + (size_t)(hr >> 1) * K + (hr & 1) * 32 + c * 4);
        }
#pragma unroll
        for (int i = 0; i < 8; i++) {          // B: 1024 16B chunks fp16
            int l = tid + i * 128;
            int row = l >> 3, kc = l & 7;
            uint32_t soff = (uint32_t)(row * 128 + ((kc ^ (row & 7)) << 4));
            cp_async16(bS + soff, Bg + (size_t)row * K + kc * 8);
        }
        cp_commit();
    };

    load_stage(0, 0);

    for (int kt = 0; kt < KT; kt++) {
        cp_wait<0>();
        __syncthreads();
        if (kt + 1 < KT) load_stage(kt + 1, (kt + 1) & 1);

        const uint32_t aS = sbase + (uint32_t)(kt & 1) * STAGE;
        const uint32_t bS = aS + ABYTES;
#pragma unroll
        for (int ks = 0; ks < 4; ks++) {
            const int hsel = ks >> 1;
            const int klo  = (ks & 1) * 4 + kBit;
            uint32_t af[4][4];
#pragma unroll
            for (int mt = 0; mt < 4; mt++) {
                uint32_t hr0 = aHr[mt] + hsel;         // rows r and r+8 share hr&7 cadence
                uint32_t base0 = aS + hr0 * 128 + aSub;
                uint32_t base1 = base0 + 16 * 128;     // +8 rows = +16 halfrows
                uint32_t x0 = (uint32_t)((klo ^ (hr0 & 7)) << 4);
                uint32_t x2 = (uint32_t)(((klo + 2) ^ (hr0 & 7)) << 4);
                float2 v0 = lds_f2(base0 + x0);
                float2 v1 = lds_f2(base1 + x0);
                float2 v2 = lds_f2(base0 + x2);
                float2 v3 = lds_f2(base1 + x2);
                __half2 h0 = __floats2half2_rn(v0.x, v0.y);
                __half2 h1 = __floats2half2_rn(v1.x, v1.y);
                __half2 h2 = __floats2half2_rn(v2.x, v2.y);
                __half2 h3 = __floats2half2_rn(v3.x, v3.y);
                af[mt][0] = *(uint32_t*)&h0;
                af[mt][1] = *(uint32_t*)&h1;
                af[mt][2] = *(uint32_t*)&h2;
                af[mt][3] = *(uint32_t*)&h3;
            }
            uint32_t bf[8][2];
#pragma unroll
            for (int np = 0; np < 4; np++) {
                uint32_t t[4];
                ldsm4(t, bS + bRowOff[np] + (uint32_t)((((2 * ks + bHi) ^ bRx[np])) * 16));
                bf[2 * np][0] = t[0]; bf[2 * np][1] = t[1];
                bf[2 * np + 1][0] = t[2]; bf[2 * np + 1][1] = t[3];
            }
#pragma unroll
            for (int mt = 0; mt < 4; mt++)
#pragma unroll
                for (int nt = 0; nt < 8; nt++)
                    mma16816(acc[mt][nt], af[mt], bf[nt]);
        }
    }

    // epilogue: h fp16
#pragma unroll
    for (int mt = 0; mt < 4; mt++) {
#pragma unroll
        for (int nt = 0; nt < 8; nt++) {
            int m0 = bm + warpM + mt * 16 + (ln >> 2);
            int n0 = bn + warpN + nt * 8 + (ln & 3) * 2;
            float* a = acc[mt][nt];
            __half2 v0 = __floats2half2_rn(a[0], a[1]);
            __half2 v1 = __floats2half2_rn(a[2], a[3]);
            *(__half2*)(C + (size_t)m0 * N + n0)       = v0;
            *(__half2*)(C + (size_t)(m0 + 8) * N + n0) = v1;
        }
    }
}

// ---------------------------------------------------------------------------
// Stage 2: out[M][D] = h[M][R] @ wout^T + bias. fp16 in, fp32 out.
// Round-4 proven config: BM=128, BN=128, BK=64, DEPTH=3, 2 CTAs/SM.
// ---------------------------------------------------------------------------
__global__ __launch_bounds__(128, 2) void gemm_s2(
    const __half* __restrict__ A, const __half* __restrict__ Bt,
    float* __restrict__ C, const float* __restrict__ bias, int K, int N)
{
    constexpr int ABYTES = 128 * 128;
    constexpr int STAGE  = 2 * ABYTES;
    constexpr int DEPTH  = 3;

    extern __shared__ __align__(1024) uint8_t dsmem[];
    const uint32_t sbase = (smem_u32(dsmem) + 1023u) & ~1023u;

    const int tid = threadIdx.x;
    const int wid = tid >> 5, ln = tid & 31;
    const int bm = blockIdx.y * 128, bn = blockIdx.x * 128;
    const int warpM = (wid >> 1) * 64;
    const int warpN = (wid & 1) * 64;

    float acc[4][8][4];
#pragma unroll
    for (int i = 0; i < 4; i++)
#pragma unroll
        for (int j = 0; j < 8; j++)
#pragma unroll
            for (int k = 0; k < 4; k++) acc[i][j][k] = 0.f;

    const int mat = ln >> 3;
    const int mr  = ln & 7;
    const int aHi = mat >> 1;
    const int bHi = mat & 1;
    uint32_t aRowOff[4]; int aRx[4];
#pragma unroll
    for (int mt = 0; mt < 4; mt++) {
        int row = warpM + mt * 16 + ((mat & 1) << 3) + mr;
        aRowOff[mt] = (uint32_t)(row * 128);
        aRx[mt] = row & 7;
    }
    uint32_t bRowOff[4]; int bRx[4];
#pragma unroll
    for (int np = 0; np < 4; np++) {
        int row = warpN + np * 16 + ((mat >> 1) << 3) + mr;
        bRowOff[np] = (uint32_t)(row * 128);
        bRx[np] = row & 7;
    }

    const int KT = K >> 6;

    auto load_stage = [&](int kt, int s) {
        const uint32_t aS = sbase + (uint32_t)s * STAGE;
        const uint32_t bS = aS + ABYTES;
        const __half* Ag = A  + (size_t)bm * K + (size_t)kt * 64;
        const __half* Bg = Bt + (size_t)bn * K + (size_t)kt * 64;
#pragma unroll
        for (int i = 0; i < 8; i++) {
            int l = tid + i * 128;
            int row = l >> 3, kc = l & 7;
            uint32_t soff = (uint32_t)(row * 128 + ((kc ^ (row & 7)) * 16));
            cp_async16(aS + soff, Ag + (size_t)row * K + kc * 8);
            cp_async16(bS + soff, Bg + (size_t)row * K + kc * 8);
        }
        cp_commit();
    };

    load_stage(0, 0);
    load_stage(1, 1);

    for (int kt = 0; kt < KT; kt++) {
        cp_wait<1>();
        __syncthreads();
        if (kt + 2 < KT) load_stage(kt + 2, (kt + 2) % DEPTH);
        else cp_commit();

        const uint32_t aB = sbase + (uint32_t)(kt % DEPTH) * STAGE;
        const uint32_t bB = aB + ABYTES;
#pragma unroll
        for (int ks = 0; ks < 4; ks++) {
            uint32_t af[4][4];
#pragma unroll
            for (int mt = 0; mt < 4; mt++)
                ldsm4(af[mt], aB + aRowOff[mt] + (uint32_t)((((2 * ks + aHi) ^ aRx[mt])) * 16));
            uint32_t bf[8][2];
#pragma unroll
            for (int np = 0; np < 4; np++) {
                uint32_t t[4];
                ldsm4(t, bB + bRowOff[np] + (uint32_t)((((2 * ks + bHi) ^ bRx[np])) * 16));
                bf[2 * np][0] = t[0]; bf[2 * np][1] = t[1];
                bf[2 * np + 1][0] = t[2]; bf[2 * np + 1][1] = t[3];
            }
#pragma unroll
            for (int mt = 0; mt < 4; mt++)
#pragma unroll
                for (int nt = 0; nt < 8; nt++)
                    mma16816(acc[mt][nt], af[mt], bf[nt]);
        }
    }

    // epilogue: fp32 + bias
#pragma unroll
    for (int mt = 0; mt < 4; mt++) {
#pragma unroll
        for (int nt = 0; nt < 8; nt++) {
            int m0 = bm + warpM + mt * 16 + (ln >> 2);
            int n0 = bn + warpN + nt * 8 + (ln & 3) * 2;
            float* a = acc[mt][nt];
            float b0 = bias[n0], b1 = bias[n0 + 1];
            float2 v0 = make_float2(a[0] + b0, a[1] + b1);
            float2 v1 = make_float2(a[2] + b0, a[3] + b1);
            *(float2*)(C + (size_t)m0 * N + n0)       = v0;
            *(float2*)(C + (size_t)(m0 + 8) * N + n0) = v1;
        }
    }
}

// ---------------------------------------------------------------------------
extern "C" void kernel_launch(void* const* d_in, const int* in_sizes, int n_in,
                              void* d_out, int out_size)
{
    const float* x    = (const float*)d_in[0];
    const float* w_in = (const float*)d_in[1];
    const float* w_out= (const float*)d_in[2];
    const float* bias = (const float*)d_in[3];
    const float* s_in = (const float*)d_in[4];
    const float* s_out= (const float*)d_in[5];
    float* out = (float*)d_out;

    __half *h, *win, *wout;
    cudaGetSymbolAddress((void**)&h,    g_h);
    cudaGetSymbolAddress((void**)&win,  g_win);
    cudaGetSymbolAddress((void**)&wout, g_wout);

    constexpr int SMEM1 = 2 * (128 * 256 + 128 * 128) + 1024;  // 2-deep, A fp32
    constexpr int SMEM2 = 3 * (2 * 128 * 128) + 1024;          // 3-deep, fp16

    cudaFuncSetAttribute(gemm_s1, cudaFuncAttributeMaxDynamicSharedMemorySize, SMEM1);
    cudaFuncSetAttribute(gemm_s2, cudaFuncAttributeMaxDynamicSharedMemorySize, SMEM2);

    // 1) soft-threshold weights into B^T fp16 layouts
    prep_win_kernel<<<(DD * (RR / 4)) / 256, 256>>>(w_in, s_in);
    prep_wout_kernel<<<((DD / 4) * RR) / 256, 256>>>(w_out, s_out);

    // 2) stage 1: h = fp16(x) @ win^T   grid (4, 64) = 256 CTAs
    {
        dim3 grid(RR / 128, MM / 128);
        gemm_s1<<<grid, 128, SMEM1>>>(x, win, h, DD, RR);
    }
    // 3) stage 2: out = h @ wout^T + bias   grid (16, 64) = 1024 CTAs
    {
        dim3 grid(DD / 128, MM / 128);
        gemm_s2<<<grid, 128, SMEM2>>>(h, wout, out, bias, RR, DD);
    }
}